// round 1
// baseline (speedup 1.0000x reference)
#include <cuda_runtime.h>
#include <stdint.h>

#define NMAX   100000
#define EMAX   1600000
#define DIN    128
#define DOUT   32

// ---- scratch (no allocations allowed) ----
__device__ float g_h[NMAX * DOUT];     // x @ W
__device__ float g_deg[NMAX];          // degree (incl. self loop)
__device__ float g_dinv[NMAX];         // deg^{-1/2}
__device__ int   g_is64;               // edge_index dtype flag

// ---------------------------------------------------------------------------
// Detect whether edge_index is int64 or int32.
// If int64 (values in [0,100000), little-endian), every odd 32-bit word == 0.
// For int32 data those words are random values in [0,100000): P(all 4096 == 0)
// is ~0. Deterministic, runs every launch (graph-capture safe).
// ---------------------------------------------------------------------------
__global__ void k_detect(const unsigned* __restrict__ ei32) {
    __shared__ unsigned s_or;
    if (threadIdx.x == 0) s_or = 0u;
    __syncthreads();
    unsigned acc = 0u;
    // words 1,3,5,... up to index 8191 — safely within 3.2M elements either way
    for (int i = threadIdx.x; i < 4096; i += blockDim.x)
        acc |= ei32[2 * i + 1];
    atomicOr(&s_or, acc);
    __syncthreads();
    if (threadIdx.x == 0) g_is64 = (s_or == 0u) ? 1 : 0;
}

__device__ __forceinline__ int edge_at(const void* ei, long long idx, int is64) {
    if (is64) return (int)((const long long*)ei)[idx];
    return ((const int*)ei)[idx];
}

// ---------------------------------------------------------------------------
// deg[i] = 1 (self loop)
// ---------------------------------------------------------------------------
__global__ void k_init_deg(int n) {
    int i = blockIdx.x * blockDim.x + threadIdx.x;
    if (i < n) g_deg[i] = 1.0f;
}

// ---------------------------------------------------------------------------
// deg[dst] += 1 per edge
// ---------------------------------------------------------------------------
__global__ void k_count(const void* __restrict__ ei, int E) {
    int e = blockIdx.x * blockDim.x + threadIdx.x;
    if (e >= E) return;
    int is64 = g_is64;
    int dst = edge_at(ei, (long long)E + e, is64);
    atomicAdd(&g_deg[dst], 1.0f);
}

// ---------------------------------------------------------------------------
// h = x @ W ; dinv = rsqrt(deg) ; out = h * dinv^2 + b  (self-loop + bias)
// One warp per row. W staged in smem. x row: 4 coalesced loads/lane, then
// shfl-broadcast into the 128 FMAs.
// ---------------------------------------------------------------------------
__global__ void k_gemm(const float* __restrict__ x, const float* __restrict__ W,
                       const float* __restrict__ b, float* __restrict__ out, int n) {
    __shared__ float Ws[DIN * DOUT];
    int tid = threadIdx.x;
    for (int i = tid; i < DIN * DOUT; i += blockDim.x) Ws[i] = W[i];
    __syncthreads();

    int lane = tid & 31;
    int warp = tid >> 5;
    int row  = blockIdx.x * (blockDim.x >> 5) + warp;
    if (row >= n) return;

    float xv[4];
#pragma unroll
    for (int j = 0; j < 4; j++) xv[j] = x[(long long)row * DIN + lane + 32 * j];

    float acc = 0.0f;
#pragma unroll
    for (int j = 0; j < 4; j++) {
#pragma unroll
        for (int i = 0; i < 32; i++) {
            float xb = __shfl_sync(0xffffffffu, xv[j], i);
            acc = fmaf(xb, Ws[(j * 32 + i) * DOUT + lane], acc);
        }
    }

    g_h[row * DOUT + lane] = acc;
    float dinv = rsqrtf(g_deg[row]);
    if (lane == 0) g_dinv[row] = dinv;
    out[row * DOUT + lane] = acc * dinv * dinv + b[lane];
}

// ---------------------------------------------------------------------------
// Edge scatter: one lane per (edge, channel).
// src/dst/dinv loads are warp-uniform (L1 broadcast); h gather and the RED
// to out are coalesced 128B per warp. atomicAdd return unused -> RED.
// ---------------------------------------------------------------------------
__global__ void k_scatter(const void* __restrict__ ei, int E,
                          float* __restrict__ out) {
    long long t = (long long)blockIdx.x * blockDim.x + threadIdx.x;
    long long e = t >> 5;
    if (e >= E) return;
    int lane = (int)(t & 31);
    int is64 = g_is64;
    int src = edge_at(ei, e, is64);
    int dst = edge_at(ei, (long long)E + e, is64);
    float norm = g_dinv[src] * g_dinv[dst];
    float v = g_h[src * DOUT + lane] * norm;
    atomicAdd(&out[dst * DOUT + lane], v);
}

// ---------------------------------------------------------------------------
extern "C" void kernel_launch(void* const* d_in, const int* in_sizes, int n_in,
                              void* d_out, int out_size) {
    const float* x  = (const float*)d_in[0];
    const void*  ei = d_in[1];
    const float* W  = (const float*)d_in[2];
    const float* b  = (const float*)d_in[3];
    float* out = (float*)d_out;

    int n = in_sizes[0] / DIN;       // 100000
    int E = in_sizes[1] / 2;         // 1600000 (element count is dtype-agnostic)

    k_detect<<<1, 256>>>((const unsigned*)ei);
    k_init_deg<<<(n + 255) / 256, 256>>>(n);
    k_count<<<(E + 255) / 256, 256>>>(ei, E);
    k_gemm<<<(n + 7) / 8, 256>>>(x, W, b, out, n);

    long long threads = (long long)E * 32;
    int blocks = (int)((threads + 255) / 256);
    k_scatter<<<blocks, 256>>>(ei, E, out);
}

// round 2
// speedup vs baseline: 1.1731x; 1.1731x over previous
#include <cuda_runtime.h>
#include <stdint.h>

#define NMAX   100000
#define EMAX   1600000
#define DIN    128
#define DOUT   32
#define CAP    64        // per-node source bucket capacity (deg ~ Poisson(16))

// ---- scratch (no allocations allowed) ----
__device__ float g_h[NMAX * DOUT];        // x @ W
__device__ float g_dinv[NMAX];            // (deg)^{-1/2}, deg = in-edges + 1
__device__ int   g_fill[NMAX];            // in-edge count per dst
__device__ int   g_srcs[NMAX * CAP];      // bucketed sources per dst
__device__ int   g_is64;                  // edge_index dtype flag
__device__ int   g_ovf_cnt;               // overflow edge count (normally 0)
__device__ int   g_ovf[2 * EMAX];         // overflow (src,dst) pairs

// ---------------------------------------------------------------------------
// Detect whether edge_index is int64 or int32. For int64 values < 2^31
// (little-endian), every odd 32-bit word == 0. Deterministic each launch.
// ---------------------------------------------------------------------------
__global__ void k_detect(const unsigned* __restrict__ ei32) {
    __shared__ unsigned s_or;
    if (threadIdx.x == 0) s_or = 0u;
    __syncthreads();
    unsigned acc = 0u;
    for (int i = threadIdx.x; i < 4096; i += blockDim.x)
        acc |= ei32[2 * i + 1];
    atomicOr(&s_or, acc);
    __syncthreads();
    if (threadIdx.x == 0) g_is64 = (s_or == 0u) ? 1 : 0;
}

__device__ __forceinline__ int edge_at(const void* ei, long long idx, int is64) {
    if (is64) return (int)((const long long*)ei)[idx];
    return ((const int*)ei)[idx];
}

// ---------------------------------------------------------------------------
// Reset counters (graph replays must rebuild all state).
// ---------------------------------------------------------------------------
__global__ void k_zero(int n) {
    int i = blockIdx.x * blockDim.x + threadIdx.x;
    if (i < n) g_fill[i] = 0;
    if (i == 0) g_ovf_cnt = 0;
}

// ---------------------------------------------------------------------------
// Bucket placement: srcs[dst*CAP + slot] = src. Counts degree as a side
// effect. Overflow (slot >= CAP) edges go to a spill buffer handled by
// k_cleanup — statistically never taken for Poisson(16) degrees, but keeps
// the kernel correct for any input.
// ---------------------------------------------------------------------------
__global__ void k_place(const void* __restrict__ ei, int E) {
    int e = blockIdx.x * blockDim.x + threadIdx.x;
    if (e >= E) return;
    int is64 = g_is64;
    int src = edge_at(ei, e, is64);
    int dst = edge_at(ei, (long long)E + e, is64);
    int pos = atomicAdd(&g_fill[dst], 1);
    if (pos < CAP) {
        g_srcs[dst * CAP + pos] = src;
    } else {
        int o = atomicAdd(&g_ovf_cnt, 1);
        if (o < EMAX) { g_ovf[2 * o] = src; g_ovf[2 * o + 1] = dst; }
    }
}

// ---------------------------------------------------------------------------
// Register-tiled GEMM: h = x @ W, dinv = rsqrt(deg),
// out = h*dinv^2 + b (self-loop term + bias).
//
// 256 threads, 16 rows per block. Thread u = t&63 within rowset t>>6:
//   kchunk = u&3 (32 k-values), cpair = u>>2 (2 channels).
// Each thread holds a 32x2 W fragment in registers; x tile in smem read as
// float4; k-reduction via 2 butterfly shfls over the 4 adjacent kchunk lanes.
// ---------------------------------------------------------------------------
__global__ void k_gemm(const float* __restrict__ x, const float* __restrict__ W,
                       const float* __restrict__ b, float* __restrict__ out, int n) {
    __shared__ float Wsm[DIN * DOUT];   // 16 KB
    __shared__ float xs[16 * DIN];      // 8 KB
    int t = threadIdx.x;

    // stage W (coalesced float4)
    {
        float4* wv = (float4*)Wsm;
        const float4* wg = (const float4*)W;
        for (int i = t; i < DIN * DOUT / 4; i += 256) wv[i] = wg[i];
    }
    // stage x tile: 16 rows x 32 float4 = 512 float4
    int row0 = blockIdx.x * 16;
    {
        float4* xv = (float4*)xs;
        const float4* xg = (const float4*)x;
        for (int i = t; i < 512; i += 256) {
            int r = i >> 5, c = i & 31;
            int gr = row0 + r;
            xv[i] = (gr < n) ? xg[(size_t)gr * 32 + c] : make_float4(0.f, 0.f, 0.f, 0.f);
        }
    }
    __syncthreads();

    int u = t & 63, rowset = t >> 6;
    int kchunk = u & 3, cpair = u >> 2;
    int c0 = cpair * 2;

    // W fragment -> registers
    float w0[32], w1[32];
#pragma unroll
    for (int i = 0; i < 32; i++) {
        float2 wv = *(float2*)&Wsm[(kchunk * 32 + i) * DOUT + c0];
        w0[i] = wv.x; w1[i] = wv.y;
    }
    float2 bb = *(const float2*)&b[c0];

#pragma unroll
    for (int rr = 0; rr < 4; rr++) {
        int rl = rowset * 4 + rr;
        int row = row0 + rl;
        if (row >= n) break;
        float a0 = 0.f, a1 = 0.f;
        const float* xr = &xs[rl * DIN + kchunk * 32];
#pragma unroll
        for (int i = 0; i < 8; i++) {
            float4 xq = *(const float4*)&xr[i * 4];
            a0 = fmaf(xq.x, w0[4 * i + 0], a0);  a1 = fmaf(xq.x, w1[4 * i + 0], a1);
            a0 = fmaf(xq.y, w0[4 * i + 1], a0);  a1 = fmaf(xq.y, w1[4 * i + 1], a1);
            a0 = fmaf(xq.z, w0[4 * i + 2], a0);  a1 = fmaf(xq.z, w1[4 * i + 2], a1);
            a0 = fmaf(xq.w, w0[4 * i + 3], a0);  a1 = fmaf(xq.w, w1[4 * i + 3], a1);
        }
        // reduce across the 4 kchunk lanes (lane bits 0..1)
        a0 += __shfl_xor_sync(0xffffffffu, a0, 1);
        a1 += __shfl_xor_sync(0xffffffffu, a1, 1);
        a0 += __shfl_xor_sync(0xffffffffu, a0, 2);
        a1 += __shfl_xor_sync(0xffffffffu, a1, 2);
        if (kchunk == 0) {
            float dinv = rsqrtf(1.0f + (float)g_fill[row]);
            if (u == 0) g_dinv[row] = dinv;
            *(float2*)&g_h[row * DOUT + c0] = make_float2(a0, a1);
            float s = dinv * dinv;
            *(float2*)&out[row * DOUT + c0] =
                make_float2(fmaf(a0, s, bb.x), fmaf(a1, s, bb.y));
        }
    }
}

// ---------------------------------------------------------------------------
// Pull-side aggregation: one warp per destination node, lane = channel.
// No float atomics: only this warp writes row d. Sources loaded coalesced
// in 32-wide chunks, broadcast via shfl; 2-way unrolled for MLP.
// ---------------------------------------------------------------------------
__global__ void k_agg(float* __restrict__ out, int n) {
    int warp = threadIdx.x >> 5, lane = threadIdx.x & 31;
    int d = blockIdx.x * 8 + warp;
    if (d >= n) return;

    int cnt = g_fill[d];
    if (cnt > CAP) cnt = CAP;

    float a0 = 0.f, a1 = 0.f;
    const int* sr = &g_srcs[d * CAP];
    for (int j0 = 0; j0 < cnt; j0 += 32) {
        int m = cnt - j0; if (m > 32) m = 32;
        int   s  = (lane < m) ? sr[j0 + lane] : 0;
        float dv = (lane < m) ? g_dinv[s] : 0.f;
        int i = 0;
        for (; i + 1 < m; i += 2) {
            int   s0 = __shfl_sync(0xffffffffu, s,  i);
            int   s1 = __shfl_sync(0xffffffffu, s,  i + 1);
            float v0 = __shfl_sync(0xffffffffu, dv, i);
            float v1 = __shfl_sync(0xffffffffu, dv, i + 1);
            a0 = fmaf(g_h[s0 * DOUT + lane], v0, a0);
            a1 = fmaf(g_h[s1 * DOUT + lane], v1, a1);
        }
        if (i < m) {
            int   s0 = __shfl_sync(0xffffffffu, s,  i);
            float v0 = __shfl_sync(0xffffffffu, dv, i);
            a0 = fmaf(g_h[s0 * DOUT + lane], v0, a0);
        }
    }
    out[d * DOUT + lane] += g_dinv[d] * (a0 + a1);
}

// ---------------------------------------------------------------------------
// Overflow cleanup (normally 0 edges): scalar atomic scatter for any edge
// that didn't fit its bucket.
// ---------------------------------------------------------------------------
__global__ void k_cleanup(float* __restrict__ out) {
    int cnt = g_ovf_cnt;
    if (cnt > EMAX) cnt = EMAX;
    for (int o = blockIdx.x * blockDim.x + threadIdx.x; o < cnt;
         o += gridDim.x * blockDim.x) {
        int src = g_ovf[2 * o], dst = g_ovf[2 * o + 1];
        float nrm = g_dinv[src] * g_dinv[dst];
        for (int c = 0; c < DOUT; c++)
            atomicAdd(&out[dst * DOUT + c], g_h[src * DOUT + c] * nrm);
    }
}

// ---------------------------------------------------------------------------
extern "C" void kernel_launch(void* const* d_in, const int* in_sizes, int n_in,
                              void* d_out, int out_size) {
    const float* x  = (const float*)d_in[0];
    const void*  ei = d_in[1];
    const float* W  = (const float*)d_in[2];
    const float* b  = (const float*)d_in[3];
    float* out = (float*)d_out;

    int n = in_sizes[0] / DIN;   // 100000
    int E = in_sizes[1] / 2;     // 1600000

    k_detect<<<1, 256>>>((const unsigned*)ei);
    k_zero<<<(n + 255) / 256, 256>>>(n);
    k_place<<<(E + 255) / 256, 256>>>(ei, E);
    k_gemm<<<(n + 15) / 16, 256>>>(x, W, b, out, n);
    k_agg<<<(n + 7) / 8, 256>>>(out, n);
    k_cleanup<<<64, 256>>>(out);
}

// round 3
// speedup vs baseline: 2.8028x; 2.3893x over previous
#include <cuda_runtime.h>
#include <stdint.h>

#define NMAX   100000
#define EMAX   1600000
#define DIN    128
#define DOUT   32
#define CAP    64        // per-node source bucket capacity (deg ~ Poisson(16))
#define BM     128
#define BK     32

// ---- scratch (no allocations allowed) ----
__device__ float g_h[NMAX * DOUT];        // x @ W
__device__ float g_dinv[NMAX];            // (deg)^{-1/2}, deg = in-edges + 1
__device__ int   g_fill[NMAX];            // in-edge count per dst
__device__ int   g_srcs[NMAX * CAP];      // bucketed sources per dst
__device__ int   g_is64;                  // edge_index dtype flag
__device__ int   g_ovf_cnt;               // overflow edge count (normally 0)
__device__ int   g_ovf[2 * EMAX];         // overflow (src,dst) pairs

// ---------------------------------------------------------------------------
// Init: zero fill counters + detect edge_index dtype (int64 little-endian
// values < 2^31 have every odd 32-bit word == 0; int32 random data doesn't).
// ---------------------------------------------------------------------------
__global__ void k_init(const unsigned* __restrict__ ei32, int n) {
    int i = blockIdx.x * blockDim.x + threadIdx.x;
    if (i < n) g_fill[i] = 0;
    if (i == 0) g_ovf_cnt = 0;
    if (blockIdx.x == 0) {
        __shared__ unsigned s_or;
        if (threadIdx.x == 0) s_or = 0u;
        __syncthreads();
        unsigned acc = 0u;
        for (int j = threadIdx.x; j < 4096; j += blockDim.x)
            acc |= ei32[2 * j + 1];
        atomicOr(&s_or, acc);
        __syncthreads();
        if (threadIdx.x == 0) g_is64 = (s_or == 0u) ? 1 : 0;
    }
}

__device__ __forceinline__ int edge_at(const void* ei, long long idx, int is64) {
    if (is64) return (int)((const long long*)ei)[idx];
    return ((const int*)ei)[idx];
}

// ---------------------------------------------------------------------------
// Bucket placement: srcs[dst*CAP + slot] = src; g_fill counts full degree.
// Overflow spills to g_ovf (statistically never for Poisson(16) degrees).
// ---------------------------------------------------------------------------
__global__ void k_place(const void* __restrict__ ei, int E) {
    int e = blockIdx.x * blockDim.x + threadIdx.x;
    if (e >= E) return;
    int is64 = g_is64;
    int src = edge_at(ei, e, is64);
    int dst = edge_at(ei, (long long)E + e, is64);
    int pos = atomicAdd(&g_fill[dst], 1);
    if (pos < CAP) {
        g_srcs[dst * CAP + pos] = src;
    } else {
        int o = atomicAdd(&g_ovf_cnt, 1);
        if (o < EMAX) { g_ovf[2 * o] = src; g_ovf[2 * o + 1] = dst; }
    }
}

// ---------------------------------------------------------------------------
// GEMM: h = x @ W; out = h*dinv^2 + b (self-loop + bias); dinv side-written.
// Block tile 128x32, BK=32, 256 threads, 4x4 micro-tile per thread.
//   tx = t&7  -> cols tx*4..+3 ; ty = t>>3 -> rows ty*4..+3
// xs[BM][BK+1]: +1 pad makes the 4 scalar x-broadcast loads conflict-free
// (banks 4*ty+i+k distinct over ty). Staging: float4 LDG + 4 scalar STS
// (banks r + 4*k4 + j: all 32 distinct within a warp).
// ~40 regs -> high occupancy; FMA-pipe is the intended binder.
// ---------------------------------------------------------------------------
__global__ void k_gemm(const float* __restrict__ x, const float* __restrict__ W,
                       const float* __restrict__ b, float* __restrict__ out, int n) {
    __shared__ float xs[BM][BK + 1];   // 16.5 KB
    __shared__ float ws[BK][DOUT];     // 4 KB
    int t = threadIdx.x;
    int row0 = blockIdx.x * BM;
    int tx = t & 7, ty = t >> 3;

    float4 acc[4];
#pragma unroll
    for (int i = 0; i < 4; i++) acc[i] = make_float4(0.f, 0.f, 0.f, 0.f);

    for (int kc = 0; kc < DIN; kc += BK) {
        // stage x chunk: 128 rows x 8 float4 = 1024 float4, 4 per thread
#pragma unroll
        for (int it = 0; it < 4; it++) {
            int i = t + it * 256;
            int r = i >> 3, k4 = i & 7;
            int gr = row0 + r;
            float4 v = (gr < n)
                ? *(const float4*)&x[(size_t)gr * DIN + kc + k4 * 4]
                : make_float4(0.f, 0.f, 0.f, 0.f);
            xs[r][k4 * 4 + 0] = v.x;
            xs[r][k4 * 4 + 1] = v.y;
            xs[r][k4 * 4 + 2] = v.z;
            xs[r][k4 * 4 + 3] = v.w;
        }
        // stage W chunk: 32x32 floats = 256 float4, 1 per thread
        ((float4*)ws)[t] = ((const float4*)(W + kc * DOUT))[t];
        __syncthreads();

#pragma unroll
        for (int k = 0; k < BK; k++) {
            float a0 = xs[ty * 4 + 0][k];
            float a1 = xs[ty * 4 + 1][k];
            float a2 = xs[ty * 4 + 2][k];
            float a3 = xs[ty * 4 + 3][k];
            float4 bw = *(float4*)&ws[k][tx * 4];
            acc[0].x = fmaf(a0, bw.x, acc[0].x); acc[0].y = fmaf(a0, bw.y, acc[0].y);
            acc[0].z = fmaf(a0, bw.z, acc[0].z); acc[0].w = fmaf(a0, bw.w, acc[0].w);
            acc[1].x = fmaf(a1, bw.x, acc[1].x); acc[1].y = fmaf(a1, bw.y, acc[1].y);
            acc[1].z = fmaf(a1, bw.z, acc[1].z); acc[1].w = fmaf(a1, bw.w, acc[1].w);
            acc[2].x = fmaf(a2, bw.x, acc[2].x); acc[2].y = fmaf(a2, bw.y, acc[2].y);
            acc[2].z = fmaf(a2, bw.z, acc[2].z); acc[2].w = fmaf(a2, bw.w, acc[2].w);
            acc[3].x = fmaf(a3, bw.x, acc[3].x); acc[3].y = fmaf(a3, bw.y, acc[3].y);
            acc[3].z = fmaf(a3, bw.z, acc[3].z); acc[3].w = fmaf(a3, bw.w, acc[3].w);
        }
        __syncthreads();
    }

    float4 bb = *(const float4*)&b[tx * 4];
#pragma unroll
    for (int i = 0; i < 4; i++) {
        int row = row0 + ty * 4 + i;
        if (row >= n) break;
        *(float4*)&g_h[row * DOUT + tx * 4] = acc[i];
        float dinv = rsqrtf(1.0f + (float)g_fill[row]);
        if (tx == 0) g_dinv[row] = dinv;
        float s = dinv * dinv;
        float4 o;
        o.x = fmaf(acc[i].x, s, bb.x);
        o.y = fmaf(acc[i].y, s, bb.y);
        o.z = fmaf(acc[i].z, s, bb.z);
        o.w = fmaf(acc[i].w, s, bb.w);
        *(float4*)&out[row * DOUT + tx * 4] = o;
    }
}

// ---------------------------------------------------------------------------
// Pull-side aggregation: one warp per destination node, lane = channel.
// No float atomics. Sources loaded coalesced, broadcast via shfl, 2-way ILP.
// ---------------------------------------------------------------------------
__global__ void k_agg(float* __restrict__ out, int n) {
    int warp = threadIdx.x >> 5, lane = threadIdx.x & 31;
    int d = blockIdx.x * 8 + warp;
    if (d >= n) return;

    int cnt = g_fill[d];
    if (cnt > CAP) cnt = CAP;

    float a0 = 0.f, a1 = 0.f;
    const int* sr = &g_srcs[d * CAP];
    for (int j0 = 0; j0 < cnt; j0 += 32) {
        int m = cnt - j0; if (m > 32) m = 32;
        int   s  = (lane < m) ? sr[j0 + lane] : 0;
        float dv = (lane < m) ? g_dinv[s] : 0.f;
        int i = 0;
        for (; i + 1 < m; i += 2) {
            int   s0 = __shfl_sync(0xffffffffu, s,  i);
            int   s1 = __shfl_sync(0xffffffffu, s,  i + 1);
            float v0 = __shfl_sync(0xffffffffu, dv, i);
            float v1 = __shfl_sync(0xffffffffu, dv, i + 1);
            a0 = fmaf(g_h[s0 * DOUT + lane], v0, a0);
            a1 = fmaf(g_h[s1 * DOUT + lane], v1, a1);
        }
        if (i < m) {
            int   s0 = __shfl_sync(0xffffffffu, s,  i);
            float v0 = __shfl_sync(0xffffffffu, dv, i);
            a0 = fmaf(g_h[s0 * DOUT + lane], v0, a0);
        }
    }
    out[d * DOUT + lane] += g_dinv[d] * (a0 + a1);
}

// ---------------------------------------------------------------------------
// Overflow cleanup (normally 0 edges).
// ---------------------------------------------------------------------------
__global__ void k_cleanup(float* __restrict__ out) {
    int cnt = g_ovf_cnt;
    if (cnt > EMAX) cnt = EMAX;
    for (int o = blockIdx.x * blockDim.x + threadIdx.x; o < cnt;
         o += gridDim.x * blockDim.x) {
        int src = g_ovf[2 * o], dst = g_ovf[2 * o + 1];
        float nrm = g_dinv[src] * g_dinv[dst];
        for (int c = 0; c < DOUT; c++)
            atomicAdd(&out[dst * DOUT + c], g_h[src * DOUT + c] * nrm);
    }
}

// ---------------------------------------------------------------------------
extern "C" void kernel_launch(void* const* d_in, const int* in_sizes, int n_in,
                              void* d_out, int out_size) {
    const float* x  = (const float*)d_in[0];
    const void*  ei = d_in[1];
    const float* W  = (const float*)d_in[2];
    const float* b  = (const float*)d_in[3];
    float* out = (float*)d_out;

    int n = in_sizes[0] / DIN;   // 100000
    int E = in_sizes[1] / 2;     // 1600000

    k_init<<<(n + 255) / 256, 256>>>((const unsigned*)ei, n);
    k_place<<<(E + 255) / 256, 256>>>(ei, E);
    k_gemm<<<(n + BM - 1) / BM, 256>>>(x, W, b, out, n);
    k_agg<<<(n + 7) / 8, 256>>>(out, n);
    k_cleanup<<<64, 256>>>(out);
}

// round 4
// speedup vs baseline: 3.0412x; 1.0851x over previous
#include <cuda_runtime.h>
#include <stdint.h>

#define NMAX   100000
#define EMAX   1600000
#define DIN    128
#define DOUT   32
#define CAP    64        // per-node source bucket capacity (deg ~ Poisson(16))
#define BM     128
#define BK     32

// ---- scratch (no allocations allowed) ----
__device__ float g_h[NMAX * DOUT];        // x @ W
__device__ float g_dinv[NMAX];            // (deg)^{-1/2}, deg = in-edges + 1
__device__ int   g_fill[NMAX];            // in-edge count per dst
__device__ int   g_srcs[NMAX * CAP];      // bucketed sources per dst
__device__ int   g_is64;                  // edge_index dtype flag
__device__ int   g_ovf_cnt;               // overflow edge count (normally 0)
__device__ int   g_ovf[2 * EMAX];         // overflow (src,dst) pairs

// ---------------------------------------------------------------------------
// Init: zero fill counters + detect edge_index dtype (int64 little-endian
// values < 2^31 have every odd 32-bit word == 0; int32 random data doesn't).
// ---------------------------------------------------------------------------
__global__ void k_init(const unsigned* __restrict__ ei32, int n) {
    int i = blockIdx.x * blockDim.x + threadIdx.x;
    if (i < n) g_fill[i] = 0;
    if (i == 0) g_ovf_cnt = 0;
    if (blockIdx.x == 0) {
        __shared__ unsigned s_or;
        if (threadIdx.x == 0) s_or = 0u;
        __syncthreads();
        unsigned acc = 0u;
        for (int j = threadIdx.x; j < 4096; j += blockDim.x)
            acc |= ei32[2 * j + 1];
        atomicOr(&s_or, acc);
        __syncthreads();
        if (threadIdx.x == 0) g_is64 = (s_or == 0u) ? 1 : 0;
    }
}

__device__ __forceinline__ int edge_at(const void* ei, long long idx, int is64) {
    if (is64) return (int)((const long long*)ei)[idx];
    return ((const int*)ei)[idx];
}

// ---------------------------------------------------------------------------
// Bucket placement: srcs[dst*CAP + slot] = src; g_fill counts full degree.
// Overflow spills to g_ovf (statistically never for Poisson(16) degrees).
// ---------------------------------------------------------------------------
__global__ void k_place(const void* __restrict__ ei, int E) {
    int e = blockIdx.x * blockDim.x + threadIdx.x;
    if (e >= E) return;
    int is64 = g_is64;
    int src = edge_at(ei, e, is64);
    int dst = edge_at(ei, (long long)E + e, is64);
    int pos = atomicAdd(&g_fill[dst], 1);
    if (pos < CAP) {
        g_srcs[dst * CAP + pos] = src;
    } else {
        int o = atomicAdd(&g_ovf_cnt, 1);
        if (o < EMAX) { g_ovf[2 * o] = src; g_ovf[2 * o + 1] = dst; }
    }
}

// ---------------------------------------------------------------------------
// GEMM: h = x @ W; out = h*dinv^2 + b (self-loop + bias); dinv side-written.
// Block tile 128x32, BK=32, 256 threads, 4x4 micro-tile per thread.
// ---------------------------------------------------------------------------
__global__ void k_gemm(const float* __restrict__ x, const float* __restrict__ W,
                       const float* __restrict__ b, float* __restrict__ out, int n) {
    __shared__ float xs[BM][BK + 1];   // 16.5 KB
    __shared__ float ws[BK][DOUT];     // 4 KB
    int t = threadIdx.x;
    int row0 = blockIdx.x * BM;
    int tx = t & 7, ty = t >> 3;

    float4 acc[4];
#pragma unroll
    for (int i = 0; i < 4; i++) acc[i] = make_float4(0.f, 0.f, 0.f, 0.f);

    for (int kc = 0; kc < DIN; kc += BK) {
#pragma unroll
        for (int it = 0; it < 4; it++) {
            int i = t + it * 256;
            int r = i >> 3, k4 = i & 7;
            int gr = row0 + r;
            float4 v = (gr < n)
                ? *(const float4*)&x[(size_t)gr * DIN + kc + k4 * 4]
                : make_float4(0.f, 0.f, 0.f, 0.f);
            xs[r][k4 * 4 + 0] = v.x;
            xs[r][k4 * 4 + 1] = v.y;
            xs[r][k4 * 4 + 2] = v.z;
            xs[r][k4 * 4 + 3] = v.w;
        }
        ((float4*)ws)[t] = ((const float4*)(W + kc * DOUT))[t];
        __syncthreads();

#pragma unroll
        for (int k = 0; k < BK; k++) {
            float a0 = xs[ty * 4 + 0][k];
            float a1 = xs[ty * 4 + 1][k];
            float a2 = xs[ty * 4 + 2][k];
            float a3 = xs[ty * 4 + 3][k];
            float4 bw = *(float4*)&ws[k][tx * 4];
            acc[0].x = fmaf(a0, bw.x, acc[0].x); acc[0].y = fmaf(a0, bw.y, acc[0].y);
            acc[0].z = fmaf(a0, bw.z, acc[0].z); acc[0].w = fmaf(a0, bw.w, acc[0].w);
            acc[1].x = fmaf(a1, bw.x, acc[1].x); acc[1].y = fmaf(a1, bw.y, acc[1].y);
            acc[1].z = fmaf(a1, bw.z, acc[1].z); acc[1].w = fmaf(a1, bw.w, acc[1].w);
            acc[2].x = fmaf(a2, bw.x, acc[2].x); acc[2].y = fmaf(a2, bw.y, acc[2].y);
            acc[2].z = fmaf(a2, bw.z, acc[2].z); acc[2].w = fmaf(a2, bw.w, acc[2].w);
            acc[3].x = fmaf(a3, bw.x, acc[3].x); acc[3].y = fmaf(a3, bw.y, acc[3].y);
            acc[3].z = fmaf(a3, bw.z, acc[3].z); acc[3].w = fmaf(a3, bw.w, acc[3].w);
        }
        __syncthreads();
    }

    float4 bb = *(const float4*)&b[tx * 4];
#pragma unroll
    for (int i = 0; i < 4; i++) {
        int row = row0 + ty * 4 + i;
        if (row >= n) break;
        *(float4*)&g_h[row * DOUT + tx * 4] = acc[i];
        float dinv = rsqrtf(1.0f + (float)g_fill[row]);
        if (tx == 0) g_dinv[row] = dinv;
        float s = dinv * dinv;
        float4 o;
        o.x = fmaf(acc[i].x, s, bb.x);
        o.y = fmaf(acc[i].y, s, bb.y);
        o.z = fmaf(acc[i].z, s, bb.z);
        o.w = fmaf(acc[i].w, s, bb.w);
        *(float4*)&out[row * DOUT + tx * 4] = o;
    }
}

// ---------------------------------------------------------------------------
// Pull-side aggregation, quarter-warp vectorized:
// One warp per destination node. Lane = (q, c4): quarter q=lane>>3 handles
// edge j+q of each 4-edge group; c4=lane&7 indexes a float4 of the 32-channel
// h row. Per 4 edges: one LDG.128 per lane group (4 h rows in flight), plus
// 4-address broadcast loads of src and dinv — no per-edge shfl. 2x unrolled
// (8 edges / iter) for MLP ~6. Cross-quarter reduction: 8 shfl_xor per node.
// Lanes 0-7 do the float4 read-modify-write of out (no atomics; this warp is
// the sole writer of row d).
// ---------------------------------------------------------------------------
__global__ void k_agg(float* __restrict__ out, int n) {
    int warp = threadIdx.x >> 5, lane = threadIdx.x & 31;
    int d = blockIdx.x * 8 + warp;
    if (d >= n) return;

    int q  = lane >> 3;
    int c4 = lane & 7;

    int cnt = g_fill[d];
    if (cnt > CAP) cnt = CAP;

    const int* sr = &g_srcs[d * CAP];
    float4 acc = make_float4(0.f, 0.f, 0.f, 0.f);

    int j = 0;
    for (; j + 8 <= cnt; j += 8) {
        int s0 = sr[j + q];
        int s1 = sr[j + 4 + q];
        float dv0 = g_dinv[s0];
        float dv1 = g_dinv[s1];
        float4 h0 = *(const float4*)&g_h[s0 * DOUT + c4 * 4];
        float4 h1 = *(const float4*)&g_h[s1 * DOUT + c4 * 4];
        acc.x = fmaf(h0.x, dv0, acc.x); acc.y = fmaf(h0.y, dv0, acc.y);
        acc.z = fmaf(h0.z, dv0, acc.z); acc.w = fmaf(h0.w, dv0, acc.w);
        acc.x = fmaf(h1.x, dv1, acc.x); acc.y = fmaf(h1.y, dv1, acc.y);
        acc.z = fmaf(h1.z, dv1, acc.z); acc.w = fmaf(h1.w, dv1, acc.w);
    }
    for (; j < cnt; j += 4) {
        int e = j + q;
        if (e < cnt) {
            int s = sr[e];
            float dv = g_dinv[s];
            float4 hv = *(const float4*)&g_h[s * DOUT + c4 * 4];
            acc.x = fmaf(hv.x, dv, acc.x); acc.y = fmaf(hv.y, dv, acc.y);
            acc.z = fmaf(hv.z, dv, acc.z); acc.w = fmaf(hv.w, dv, acc.w);
        }
    }

    // reduce quarters (lane bits 3,4)
    acc.x += __shfl_xor_sync(0xffffffffu, acc.x, 8);
    acc.y += __shfl_xor_sync(0xffffffffu, acc.y, 8);
    acc.z += __shfl_xor_sync(0xffffffffu, acc.z, 8);
    acc.w += __shfl_xor_sync(0xffffffffu, acc.w, 8);
    acc.x += __shfl_xor_sync(0xffffffffu, acc.x, 16);
    acc.y += __shfl_xor_sync(0xffffffffu, acc.y, 16);
    acc.z += __shfl_xor_sync(0xffffffffu, acc.z, 16);
    acc.w += __shfl_xor_sync(0xffffffffu, acc.w, 16);

    if (lane < 8) {
        float dd = g_dinv[d];
        float4* op = (float4*)&out[d * DOUT + lane * 4];
        float4 o = *op;
        o.x = fmaf(acc.x, dd, o.x);
        o.y = fmaf(acc.y, dd, o.y);
        o.z = fmaf(acc.z, dd, o.z);
        o.w = fmaf(acc.w, dd, o.w);
        *op = o;
    }
}

// ---------------------------------------------------------------------------
// Overflow cleanup (normally 0 edges).
// ---------------------------------------------------------------------------
__global__ void k_cleanup(float* __restrict__ out) {
    int cnt = g_ovf_cnt;
    if (cnt > EMAX) cnt = EMAX;
    for (int o = blockIdx.x * blockDim.x + threadIdx.x; o < cnt;
         o += gridDim.x * blockDim.x) {
        int src = g_ovf[2 * o], dst = g_ovf[2 * o + 1];
        float nrm = g_dinv[src] * g_dinv[dst];
        for (int c = 0; c < DOUT; c++)
            atomicAdd(&out[dst * DOUT + c], g_h[src * DOUT + c] * nrm);
    }
}

// ---------------------------------------------------------------------------
extern "C" void kernel_launch(void* const* d_in, const int* in_sizes, int n_in,
                              void* d_out, int out_size) {
    const float* x  = (const float*)d_in[0];
    const void*  ei = d_in[1];
    const float* W  = (const float*)d_in[2];
    const float* b  = (const float*)d_in[3];
    float* out = (float*)d_out;

    int n = in_sizes[0] / DIN;   // 100000
    int E = in_sizes[1] / 2;     // 1600000

    k_init<<<(n + 255) / 256, 256>>>((const unsigned*)ei, n);
    k_place<<<(E + 255) / 256, 256>>>(ei, E);
    k_gemm<<<(n + BM - 1) / BM, 256>>>(x, W, b, out, n);
    k_agg<<<(n + 7) / 8, 256>>>(out, n);
    k_cleanup<<<16, 256>>>(out);
}

// round 5
// speedup vs baseline: 3.2370x; 1.0644x over previous
#include <cuda_runtime.h>
#include <stdint.h>

#define NMAX   100000
#define EMAX   1600000
#define DIN    128
#define DOUT   32
#define CAP    64        // per-node source bucket capacity (deg ~ Poisson(16))
#define BM     128
#define BK     32

// ---- scratch (no allocations allowed) ----
__device__ float g_h[NMAX * DOUT];        // (x @ W) * dinv[row]  (pre-scaled!)
__device__ float g_dinv[NMAX];            // (deg)^{-1/2}, deg = in-edges + 1
__device__ int   g_fill[NMAX];            // in-edge count per dst
__device__ int   g_srcs[NMAX * CAP];      // bucketed sources per dst
__device__ int   g_is64;                  // edge_index dtype flag
__device__ int   g_ovf_cnt;               // overflow edge count (normally 0)
__device__ int   g_ovf[2 * EMAX];         // overflow (src,dst) pairs

// ---------------------------------------------------------------------------
// Init: zero fill counters + detect edge_index dtype (int64 little-endian
// values < 2^31 have every odd 32-bit word == 0; int32 random data doesn't).
// ---------------------------------------------------------------------------
__global__ void k_init(const unsigned* __restrict__ ei32, int n) {
    int i = blockIdx.x * blockDim.x + threadIdx.x;
    if (i < n) g_fill[i] = 0;
    if (i == 0) g_ovf_cnt = 0;
    if (blockIdx.x == 0) {
        __shared__ unsigned s_or;
        if (threadIdx.x == 0) s_or = 0u;
        __syncthreads();
        unsigned acc = 0u;
        for (int j = threadIdx.x; j < 4096; j += blockDim.x)
            acc |= ei32[2 * j + 1];
        atomicOr(&s_or, acc);
        __syncthreads();
        if (threadIdx.x == 0) g_is64 = (s_or == 0u) ? 1 : 0;
    }
}

__device__ __forceinline__ int edge_at(const void* ei, long long idx, int is64) {
    if (is64) return (int)((const long long*)ei)[idx];
    return ((const int*)ei)[idx];
}

// ---------------------------------------------------------------------------
// Bucket placement: srcs[dst*CAP + slot] = src; g_fill counts full degree.
// ---------------------------------------------------------------------------
__global__ void k_place(const void* __restrict__ ei, int E) {
    int e = blockIdx.x * blockDim.x + threadIdx.x;
    if (e >= E) return;
    int is64 = g_is64;
    int src = edge_at(ei, e, is64);
    int dst = edge_at(ei, (long long)E + e, is64);
    int pos = atomicAdd(&g_fill[dst], 1);
    if (pos < CAP) {
        g_srcs[dst * CAP + pos] = src;
    } else {
        int o = atomicAdd(&g_ovf_cnt, 1);
        if (o < EMAX) { g_ovf[2 * o] = src; g_ovf[2 * o + 1] = dst; }
    }
}

// ---------------------------------------------------------------------------
// GEMM: acc = x @ W. Stores g_h = acc * dinv (source-side norm folded in,
// so k_agg never loads dinv per edge) and out = acc*dinv^2 + b (self-loop).
// Block tile 128x32, BK=32, 256 threads, 4x4 micro-tile per thread.
// ---------------------------------------------------------------------------
__global__ void k_gemm(const float* __restrict__ x, const float* __restrict__ W,
                       const float* __restrict__ b, float* __restrict__ out, int n) {
    __shared__ float xs[BM][BK + 1];   // 16.5 KB
    __shared__ float ws[BK][DOUT];     // 4 KB
    int t = threadIdx.x;
    int row0 = blockIdx.x * BM;
    int tx = t & 7, ty = t >> 3;

    float4 acc[4];
#pragma unroll
    for (int i = 0; i < 4; i++) acc[i] = make_float4(0.f, 0.f, 0.f, 0.f);

    for (int kc = 0; kc < DIN; kc += BK) {
#pragma unroll
        for (int it = 0; it < 4; it++) {
            int i = t + it * 256;
            int r = i >> 3, k4 = i & 7;
            int gr = row0 + r;
            float4 v = (gr < n)
                ? *(const float4*)&x[(size_t)gr * DIN + kc + k4 * 4]
                : make_float4(0.f, 0.f, 0.f, 0.f);
            xs[r][k4 * 4 + 0] = v.x;
            xs[r][k4 * 4 + 1] = v.y;
            xs[r][k4 * 4 + 2] = v.z;
            xs[r][k4 * 4 + 3] = v.w;
        }
        ((float4*)ws)[t] = ((const float4*)(W + kc * DOUT))[t];
        __syncthreads();

#pragma unroll
        for (int k = 0; k < BK; k++) {
            float a0 = xs[ty * 4 + 0][k];
            float a1 = xs[ty * 4 + 1][k];
            float a2 = xs[ty * 4 + 2][k];
            float a3 = xs[ty * 4 + 3][k];
            float4 bw = *(float4*)&ws[k][tx * 4];
            acc[0].x = fmaf(a0, bw.x, acc[0].x); acc[0].y = fmaf(a0, bw.y, acc[0].y);
            acc[0].z = fmaf(a0, bw.z, acc[0].z); acc[0].w = fmaf(a0, bw.w, acc[0].w);
            acc[1].x = fmaf(a1, bw.x, acc[1].x); acc[1].y = fmaf(a1, bw.y, acc[1].y);
            acc[1].z = fmaf(a1, bw.z, acc[1].z); acc[1].w = fmaf(a1, bw.w, acc[1].w);
            acc[2].x = fmaf(a2, bw.x, acc[2].x); acc[2].y = fmaf(a2, bw.y, acc[2].y);
            acc[2].z = fmaf(a2, bw.z, acc[2].z); acc[2].w = fmaf(a2, bw.w, acc[2].w);
            acc[3].x = fmaf(a3, bw.x, acc[3].x); acc[3].y = fmaf(a3, bw.y, acc[3].y);
            acc[3].z = fmaf(a3, bw.z, acc[3].z); acc[3].w = fmaf(a3, bw.w, acc[3].w);
        }
        __syncthreads();
    }

    float4 bb = *(const float4*)&b[tx * 4];
#pragma unroll
    for (int i = 0; i < 4; i++) {
        int row = row0 + ty * 4 + i;
        if (row >= n) break;
        float dinv = rsqrtf(1.0f + (float)g_fill[row]);
        if (tx == 0) g_dinv[row] = dinv;
        float4 hs;
        hs.x = acc[i].x * dinv; hs.y = acc[i].y * dinv;
        hs.z = acc[i].z * dinv; hs.w = acc[i].w * dinv;
        *(float4*)&g_h[row * DOUT + tx * 4] = hs;
        float4 o;
        o.x = fmaf(hs.x, dinv, bb.x);
        o.y = fmaf(hs.y, dinv, bb.y);
        o.z = fmaf(hs.z, dinv, bb.z);
        o.w = fmaf(hs.w, dinv, bb.w);
        *(float4*)&out[row * DOUT + tx * 4] = o;
    }
}

// ---------------------------------------------------------------------------
// Pull-side aggregation, quarter-warp vectorized, deep MLP:
// One warp per destination, 4 warps/block (fine-grain load balance).
// Quarter q handles edge j+4i+q; lanes c4=lane&7 cover the 32 channels as
// float4. 16-edge main body front-batches all 4 src loads, then issues 4
// independent float4 h gathers (h pre-scaled by dinv[src] in k_gemm — no
// per-edge dinv load). Two accumulators split the FMA chains. Final: 8
// shfl_xor per node + float4 RMW of out by lanes 0-7 (sole writer, no
// atomics).
// ---------------------------------------------------------------------------
__global__ void __launch_bounds__(128) k_agg(float* __restrict__ out, int n) {
    int warp = threadIdx.x >> 5, lane = threadIdx.x & 31;
    int d = blockIdx.x * 4 + warp;
    if (d >= n) return;

    int q  = lane >> 3;
    int c4 = lane & 7;

    int cnt = g_fill[d];
    if (cnt > CAP) cnt = CAP;

    const int* sr = &g_srcs[d * CAP];
    float4 acc0 = make_float4(0.f, 0.f, 0.f, 0.f);
    float4 acc1 = make_float4(0.f, 0.f, 0.f, 0.f);

    int j = 0;
    for (; j + 16 <= cnt; j += 16) {
        int s0 = sr[j + q];
        int s1 = sr[j + 4 + q];
        int s2 = sr[j + 8 + q];
        int s3 = sr[j + 12 + q];
        float4 h0 = *(const float4*)&g_h[s0 * DOUT + c4 * 4];
        float4 h1 = *(const float4*)&g_h[s1 * DOUT + c4 * 4];
        float4 h2 = *(const float4*)&g_h[s2 * DOUT + c4 * 4];
        float4 h3 = *(const float4*)&g_h[s3 * DOUT + c4 * 4];
        acc0.x += h0.x; acc0.y += h0.y; acc0.z += h0.z; acc0.w += h0.w;
        acc1.x += h1.x; acc1.y += h1.y; acc1.z += h1.z; acc1.w += h1.w;
        acc0.x += h2.x; acc0.y += h2.y; acc0.z += h2.z; acc0.w += h2.w;
        acc1.x += h3.x; acc1.y += h3.y; acc1.z += h3.z; acc1.w += h3.w;
    }
    if (j + 8 <= cnt) {
        int s0 = sr[j + q];
        int s1 = sr[j + 4 + q];
        float4 h0 = *(const float4*)&g_h[s0 * DOUT + c4 * 4];
        float4 h1 = *(const float4*)&g_h[s1 * DOUT + c4 * 4];
        acc0.x += h0.x; acc0.y += h0.y; acc0.z += h0.z; acc0.w += h0.w;
        acc1.x += h1.x; acc1.y += h1.y; acc1.z += h1.z; acc1.w += h1.w;
        j += 8;
    }
    for (; j < cnt; j += 4) {
        int e = j + q;
        if (e < cnt) {
            int s = sr[e];
            float4 hv = *(const float4*)&g_h[s * DOUT + c4 * 4];
            acc0.x += hv.x; acc0.y += hv.y; acc0.z += hv.z; acc0.w += hv.w;
        }
    }

    acc0.x += acc1.x; acc0.y += acc1.y; acc0.z += acc1.z; acc0.w += acc1.w;

    // reduce quarters (lane bits 3,4)
    acc0.x += __shfl_xor_sync(0xffffffffu, acc0.x, 8);
    acc0.y += __shfl_xor_sync(0xffffffffu, acc0.y, 8);
    acc0.z += __shfl_xor_sync(0xffffffffu, acc0.z, 8);
    acc0.w += __shfl_xor_sync(0xffffffffu, acc0.w, 8);
    acc0.x += __shfl_xor_sync(0xffffffffu, acc0.x, 16);
    acc0.y += __shfl_xor_sync(0xffffffffu, acc0.y, 16);
    acc0.z += __shfl_xor_sync(0xffffffffu, acc0.z, 16);
    acc0.w += __shfl_xor_sync(0xffffffffu, acc0.w, 16);

    if (lane < 8) {
        float dd = g_dinv[d];
        float4* op = (float4*)&out[d * DOUT + lane * 4];
        float4 o = *op;
        o.x = fmaf(acc0.x, dd, o.x);
        o.y = fmaf(acc0.y, dd, o.y);
        o.z = fmaf(acc0.z, dd, o.z);
        o.w = fmaf(acc0.w, dd, o.w);
        *op = o;
    }
}

// ---------------------------------------------------------------------------
// Overflow cleanup (normally 0 edges). g_h already carries dinv[src].
// ---------------------------------------------------------------------------
__global__ void k_cleanup(float* __restrict__ out) {
    int cnt = g_ovf_cnt;
    if (cnt > EMAX) cnt = EMAX;
    for (int o = blockIdx.x * blockDim.x + threadIdx.x; o < cnt;
         o += gridDim.x * blockDim.x) {
        int src = g_ovf[2 * o], dst = g_ovf[2 * o + 1];
        float nrm = g_dinv[dst];
        for (int c = 0; c < DOUT; c++)
            atomicAdd(&out[dst * DOUT + c], g_h[src * DOUT + c] * nrm);
    }
}

// ---------------------------------------------------------------------------
extern "C" void kernel_launch(void* const* d_in, const int* in_sizes, int n_in,
                              void* d_out, int out_size) {
    const float* x  = (const float*)d_in[0];
    const void*  ei = d_in[1];
    const float* W  = (const float*)d_in[2];
    const float* b  = (const float*)d_in[3];
    float* out = (float*)d_out;

    int n = in_sizes[0] / DIN;   // 100000
    int E = in_sizes[1] / 2;     // 1600000

    k_init<<<(n + 255) / 256, 256>>>((const unsigned*)ei, n);
    k_place<<<(E + 255) / 256, 256>>>(ei, E);
    k_gemm<<<(n + BM - 1) / BM, 256>>>(x, W, b, out, n);
    k_agg<<<(n + 3) / 4, 128>>>(out, n);
    k_cleanup<<<16, 256>>>(out);
}

// round 7
// speedup vs baseline: 3.4874x; 1.0774x over previous
#include <cuda_runtime.h>
#include <stdint.h>

#define NMAX   100000
#define EMAX   1600000
#define DIN    128
#define DOUT   32
#define CAP    64        // per-node source bucket capacity (deg ~ Poisson(16))
#define BM     128
#define BK     32

// ---- scratch (no allocations allowed) ----
__device__ float g_h[NMAX * DOUT];        // (x @ W) * dinv[row]  (pre-scaled)
__device__ float g_dinv[NMAX];            // (deg)^{-1/2}, deg = in-edges + 1
__device__ int   g_fill[NMAX];            // in-edge count per dst
__device__ int   g_srcs[NMAX * CAP];      // bucketed sources per dst
__device__ int   g_is64;                  // edge_index dtype flag
__device__ int   g_ovf_cnt;               // overflow edge count (normally 0)
__device__ int   g_ovf[2 * EMAX];         // overflow (src,dst) pairs

// ---------------------------------------------------------------------------
// Init: zero fill counters + detect edge_index dtype (int64 little-endian
// values < 2^31 have every odd 32-bit word == 0; int32 random data doesn't).
// ---------------------------------------------------------------------------
__global__ void k_init(const unsigned* __restrict__ ei32, int n) {
    int i = blockIdx.x * blockDim.x + threadIdx.x;
    if (i < n) g_fill[i] = 0;
    if (i == 0) g_ovf_cnt = 0;
    if (blockIdx.x == 0) {
        __shared__ unsigned s_or;
        if (threadIdx.x == 0) s_or = 0u;
        __syncthreads();
        unsigned acc = 0u;
        for (int j = threadIdx.x; j < 4096; j += blockDim.x)
            acc |= ei32[2 * j + 1];
        atomicOr(&s_or, acc);
        __syncthreads();
        if (threadIdx.x == 0) g_is64 = (s_or == 0u) ? 1 : 0;
    }
}

__device__ __forceinline__ int edge_at(const void* ei, long long idx, int is64) {
    if (is64) return (int)((const long long*)ei)[idx];
    return ((const int*)ei)[idx];
}

// ---------------------------------------------------------------------------
// Bucket placement: srcs[dst*CAP + slot] = src; g_fill counts full degree.
// ---------------------------------------------------------------------------
__global__ void k_place(const void* __restrict__ ei, int E) {
    int e = blockIdx.x * blockDim.x + threadIdx.x;
    if (e >= E) return;
    int is64 = g_is64;
    int src = edge_at(ei, e, is64);
    int dst = edge_at(ei, (long long)E + e, is64);
    int pos = atomicAdd(&g_fill[dst], 1);
    if (pos < CAP) {
        g_srcs[dst * CAP + pos] = src;
    } else {
        int o = atomicAdd(&g_ovf_cnt, 1);
        if (o < EMAX) { g_ovf[2 * o] = src; g_ovf[2 * o + 1] = dst; }
    }
}

// ---------------------------------------------------------------------------
// GEMM: acc = x @ W. Stores g_h = acc * dinv (source-side norm folded in)
// and out = acc*dinv^2 + b (self-loop + bias).
// Block tile 128x32, BK=32, 256 threads, 4x4 micro-tile per thread.
// ---------------------------------------------------------------------------
__global__ void k_gemm(const float* __restrict__ x, const float* __restrict__ W,
                       const float* __restrict__ b, float* __restrict__ out, int n) {
    __shared__ float xs[BM][BK + 1];   // 16.5 KB
    __shared__ float ws[BK][DOUT];     // 4 KB
    int t = threadIdx.x;
    int row0 = blockIdx.x * BM;
    int tx = t & 7, ty = t >> 3;

    float4 acc[4];
#pragma unroll
    for (int i = 0; i < 4; i++) acc[i] = make_float4(0.f, 0.f, 0.f, 0.f);

    for (int kc = 0; kc < DIN; kc += BK) {
#pragma unroll
        for (int it = 0; it < 4; it++) {
            int i = t + it * 256;
            int r = i >> 3, k4 = i & 7;
            int gr = row0 + r;
            float4 v = (gr < n)
                ? *(const float4*)&x[(size_t)gr * DIN + kc + k4 * 4]
                : make_float4(0.f, 0.f, 0.f, 0.f);
            xs[r][k4 * 4 + 0] = v.x;
            xs[r][k4 * 4 + 1] = v.y;
            xs[r][k4 * 4 + 2] = v.z;
            xs[r][k4 * 4 + 3] = v.w;
        }
        ((float4*)ws)[t] = ((const float4*)(W + kc * DOUT))[t];
        __syncthreads();

#pragma unroll
        for (int k = 0; k < BK; k++) {
            float a0 = xs[ty * 4 + 0][k];
            float a1 = xs[ty * 4 + 1][k];
            float a2 = xs[ty * 4 + 2][k];
            float a3 = xs[ty * 4 + 3][k];
            float4 bw = *(float4*)&ws[k][tx * 4];
            acc[0].x = fmaf(a0, bw.x, acc[0].x); acc[0].y = fmaf(a0, bw.y, acc[0].y);
            acc[0].z = fmaf(a0, bw.z, acc[0].z); acc[0].w = fmaf(a0, bw.w, acc[0].w);
            acc[1].x = fmaf(a1, bw.x, acc[1].x); acc[1].y = fmaf(a1, bw.y, acc[1].y);
            acc[1].z = fmaf(a1, bw.z, acc[1].z); acc[1].w = fmaf(a1, bw.w, acc[1].w);
            acc[2].x = fmaf(a2, bw.x, acc[2].x); acc[2].y = fmaf(a2, bw.y, acc[2].y);
            acc[2].z = fmaf(a2, bw.z, acc[2].z); acc[2].w = fmaf(a2, bw.w, acc[2].w);
            acc[3].x = fmaf(a3, bw.x, acc[3].x); acc[3].y = fmaf(a3, bw.y, acc[3].y);
            acc[3].z = fmaf(a3, bw.z, acc[3].z); acc[3].w = fmaf(a3, bw.w, acc[3].w);
        }
        __syncthreads();
    }

    float4 bb = *(const float4*)&b[tx * 4];
#pragma unroll
    for (int i = 0; i < 4; i++) {
        int row = row0 + ty * 4 + i;
        if (row >= n) break;
        float dinv = rsqrtf(1.0f + (float)g_fill[row]);
        if (tx == 0) g_dinv[row] = dinv;
        float4 hs;
        hs.x = acc[i].x * dinv; hs.y = acc[i].y * dinv;
        hs.z = acc[i].z * dinv; hs.w = acc[i].w * dinv;
        *(float4*)&g_h[row * DOUT + tx * 4] = hs;
        float4 o;
        o.x = fmaf(hs.x, dinv, bb.x);
        o.y = fmaf(hs.y, dinv, bb.y);
        o.z = fmaf(hs.z, dinv, bb.z);
        o.w = fmaf(hs.w, dinv, bb.w);
        *(float4*)&out[row * DOUT + tx * 4] = o;
    }
}

// ---------------------------------------------------------------------------
// Pull-side aggregation with SPECULATIVE front batch:
// One warp per destination; quarter q owns edges j+q (mod 4), lanes c4=lane&7
// cover 32 channels as float4.
//
// Latency fix: srcs addresses depend only on d, not cnt. The first 16 src
// loads, cnt, dinv[d], and the out[d] row are ALL issued in parallel (1 L2
// trip wide), then 16 h-rows gathered speculatively (index clamped into
// [0,NMAX) for unconditional memory safety) and accumulated under the cnt
// predicate. Chain depth per node: 2 L2 trips (was ~4-5).
// Tail (cnt>16, ~47% of nodes) runs in 8-edge groups to bound waste.
// ---------------------------------------------------------------------------
__device__ __forceinline__ int clampidx(int s) {
    // branch-free clamp into [0, NMAX): safe even if slot holds garbage
    unsigned u = (unsigned)s;
    return (u < (unsigned)NMAX) ? s : 0;
}

__global__ void __launch_bounds__(128) k_agg(float* __restrict__ out, int n) {
    int warp = threadIdx.x >> 5, lane = threadIdx.x & 31;
    int d = blockIdx.x * 4 + warp;
    if (d >= n) return;

    int q  = lane >> 3;
    int c4 = lane & 7;

    const int* sr = &g_srcs[d * CAP];

    // --- parallel front batch: all independent of each other ---
    int s0 = clampidx(sr[q]);
    int s1 = clampidx(sr[4 + q]);
    int s2 = clampidx(sr[8 + q]);
    int s3 = clampidx(sr[12 + q]);
    int cnt_raw = g_fill[d];
    float dd = g_dinv[d];
    float4* op = (float4*)&out[d * DOUT + c4 * 4];
    float4 oval = *op;                       // hoisted out-row read (lanes<8 use it)

    // --- speculative h gathers (depend only on srcs) ---
    float4 h0 = *(const float4*)&g_h[s0 * DOUT + c4 * 4];
    float4 h1 = *(const float4*)&g_h[s1 * DOUT + c4 * 4];
    float4 h2 = *(const float4*)&g_h[s2 * DOUT + c4 * 4];
    float4 h3 = *(const float4*)&g_h[s3 * DOUT + c4 * 4];

    int cnt = cnt_raw > CAP ? CAP : cnt_raw;

    float4 a0 = make_float4(0.f, 0.f, 0.f, 0.f);
    float4 a1 = make_float4(0.f, 0.f, 0.f, 0.f);
    if (q      < cnt) { a0.x += h0.x; a0.y += h0.y; a0.z += h0.z; a0.w += h0.w; }
    if (4 + q  < cnt) { a1.x += h1.x; a1.y += h1.y; a1.z += h1.z; a1.w += h1.w; }
    if (8 + q  < cnt) { a0.x += h2.x; a0.y += h2.y; a0.z += h2.z; a0.w += h2.w; }
    if (12 + q < cnt) { a1.x += h3.x; a1.y += h3.y; a1.z += h3.z; a1.w += h3.w; }

    // --- tail: 8-edge groups, speculative loads, predicated accumulate ---
    for (int j = 16; j < cnt; j += 8) {
        int t0 = clampidx(sr[j + q]);        // j+q..j+7+q < CAP always (j<=56)
        int t1 = clampidx(sr[j + 4 + q]);
        float4 g0 = *(const float4*)&g_h[t0 * DOUT + c4 * 4];
        float4 g1 = *(const float4*)&g_h[t1 * DOUT + c4 * 4];
        if (j + q     < cnt) { a0.x += g0.x; a0.y += g0.y; a0.z += g0.z; a0.w += g0.w; }
        if (j + 4 + q < cnt) { a1.x += g1.x; a1.y += g1.y; a1.z += g1.z; a1.w += g1.w; }
    }

    a0.x += a1.x; a0.y += a1.y; a0.z += a1.z; a0.w += a1.w;

    // reduce quarters (lane bits 3,4)
    a0.x += __shfl_xor_sync(0xffffffffu, a0.x, 8);
    a0.y += __shfl_xor_sync(0xffffffffu, a0.y, 8);
    a0.z += __shfl_xor_sync(0xffffffffu, a0.z, 8);
    a0.w += __shfl_xor_sync(0xffffffffu, a0.w, 8);
    a0.x += __shfl_xor_sync(0xffffffffu, a0.x, 16);
    a0.y += __shfl_xor_sync(0xffffffffu, a0.y, 16);
    a0.z += __shfl_xor_sync(0xffffffffu, a0.z, 16);
    a0.w += __shfl_xor_sync(0xffffffffu, a0.w, 16);

    if (lane < 8) {
        oval.x = fmaf(a0.x, dd, oval.x);
        oval.y = fmaf(a0.y, dd, oval.y);
        oval.z = fmaf(a0.z, dd, oval.z);
        oval.w = fmaf(a0.w, dd, oval.w);
        *op = oval;
    }
}

// ---------------------------------------------------------------------------
// Overflow cleanup (normally 0 edges). g_h already carries dinv[src].
// ---------------------------------------------------------------------------
__global__ void k_cleanup(float* __restrict__ out) {
    int cnt = g_ovf_cnt;
    if (cnt > EMAX) cnt = EMAX;
    for (int o = blockIdx.x * blockDim.x + threadIdx.x; o < cnt;
         o += gridDim.x * blockDim.x) {
        int src = g_ovf[2 * o], dst = g_ovf[2 * o + 1];
        float nrm = g_dinv[dst];
        for (int c = 0; c < DOUT; c++)
            atomicAdd(&out[dst * DOUT + c], g_h[src * DOUT + c] * nrm);
    }
}

// ---------------------------------------------------------------------------
extern "C" void kernel_launch(void* const* d_in, const int* in_sizes, int n_in,
                              void* d_out, int out_size) {
    const float* x  = (const float*)d_in[0];
    const void*  ei = d_in[1];
    const float* W  = (const float*)d_in[2];
    const float* b  = (const float*)d_in[3];
    float* out = (float*)d_out;

    int n = in_sizes[0] / DIN;   // 100000
    int E = in_sizes[1] / 2;     // 1600000

    k_init<<<(n + 255) / 256, 256>>>((const unsigned*)ei, n);
    k_place<<<(E + 255) / 256, 256>>>(ei, E);
    k_gemm<<<(n + BM - 1) / BM, 256>>>(x, W, b, out, n);
    k_agg<<<(n + 3) / 4, 128>>>(out, n);
    k_cleanup<<<16, 256>>>(out);
}